// round 4
// baseline (speedup 1.0000x reference)
#include <cuda_runtime.h>

#define BB 32
#define CC 256
#define NN 4096
#define EE 256
#define NH 8
#define HD 32
#define NCH 16     // n-chunks
#define CHN 256    // n per chunk

// ---------------- scratch ----------------
__device__ float g_mean[BB * CC];
__device__ float g_wq[BB * CC * NH];         // [b][c][h], pre-scaled by 1/sqrt(32)
__device__ float g_cbias[BB * NH];
__device__ float g_WvT[CC * EE];             // [c][e]
__device__ float g_part[BB * NCH * 32];      // per (b,ch): m[8], s[8], px[8], py[8]
__device__ float g_xap[BB * NCH * CC * NH];  // unnormalized partial xa: [c][h]

// ---------------- K1: spatial mean (+ Wv transpose in tail blocks) -------------
__global__ void k_mean_wvt(const float* __restrict__ x, const float* __restrict__ Wv) {
    if (blockIdx.x >= BB * CC) {
        int c = blockIdx.x - BB * CC;
        g_WvT[c * EE + threadIdx.x] = Wv[threadIdx.x * CC + c];
        return;
    }
    int row = blockIdx.x;
    const float4* xr = (const float4*)(x + (size_t)row * NN);
    float4 v0 = xr[threadIdx.x];
    float4 v1 = xr[threadIdx.x + 256];
    float4 v2 = xr[threadIdx.x + 512];
    float4 v3 = xr[threadIdx.x + 768];
    float s = ((v0.x + v0.y) + (v0.z + v0.w)) + ((v1.x + v1.y) + (v1.z + v1.w))
            + ((v2.x + v2.y) + (v2.z + v2.w)) + ((v3.x + v3.y) + (v3.z + v3.w));
#pragma unroll
    for (int m = 16; m; m >>= 1) s += __shfl_xor_sync(0xffffffffu, s, m);
    __shared__ float red[8];
    if ((threadIdx.x & 31) == 0) red[threadIdx.x >> 5] = s;
    __syncthreads();
    if (threadIdx.x == 0) {
        float t = red[0];
#pragma unroll
        for (int w = 1; w < 8; ++w) t += red[w];
        g_mean[row] = t * (1.f / NN);
    }
}

// ---------------- K2: q, wq_eff, cbias ----------------
__global__ void k_qk(const float* __restrict__ Wq, const float* __restrict__ bq,
                     const float* __restrict__ Wk, const float* __restrict__ bk) {
    int b = blockIdx.x;
    int tid = threadIdx.x;
    __shared__ float mean_s[CC];
    __shared__ float q_s[EE];
    mean_s[tid] = g_mean[b * CC + tid];
    __syncthreads();
    float acc = bq[tid];
    const float* wr = Wq + (size_t)tid * CC;
#pragma unroll 4
    for (int c = 0; c < CC; ++c) acc += mean_s[c] * wr[c];
    q_s[tid] = acc;
    __syncthreads();

    const float invs = 0.17677669529663689f; // 1/sqrt(32)
    int c = tid;
#pragma unroll
    for (int h = 0; h < NH; ++h) {
        float s = 0.f;
#pragma unroll 8
        for (int d = 0; d < HD; ++d)
            s += q_s[h * HD + d] * Wk[(size_t)(h * HD + d) * CC + c];
        g_wq[(b * CC + c) * NH + h] = s * invs;
    }
    if (tid < NH) {
        float s = 0.f;
        for (int d = 0; d < HD; ++d) s += q_s[tid * HD + d] * bk[tid * HD + d];
        g_cbias[b * NH + tid] = s * invs;
    }
}

// ---------------- K3: fused logits + chunk stats + partial xa ------------------
__global__ void __launch_bounds__(256, 2) k_fused(const float* __restrict__ x,
                                                  float* __restrict__ o_attn) {
    int b = blockIdx.y, ch = blockIdx.x;
    int tid = threadIdx.x;            // 256
    int q = tid >> 6, nt = tid & 63;  // c-quarter, n-thread

    __shared__ float wq_s[CC * NH];        // 8 KB
    __shared__ float4 red4[1024];          // 16 KB (2 buffers of 512)
    __shared__ float4 a_s4[NH * 64];       // 8 KB : e-weights [h][n/4]
    __shared__ float cb_s[NH];
    __shared__ float rs_max[2][NH];
    __shared__ float rs_sum[2][24];
    __shared__ float bmax[NH];

#pragma unroll
    for (int i = 0; i < 8; ++i) wq_s[tid + i * 256] = g_wq[b * CC * NH + tid + i * 256];
    if (tid < NH) cb_s[tid] = g_cbias[b * NH + tid];
    __syncthreads();

    const float* xb = x + (size_t)b * CC * NN;
    int gn0 = ch * CHN + nt * 4;

    // ---- phase 1: logits partial over this c-quarter ----
    float acc[4][NH];
#pragma unroll
    for (int i = 0; i < 4; ++i)
#pragma unroll
        for (int h = 0; h < NH; ++h) acc[i][h] = 0.f;

    int cbase = q * 64;
    for (int c0 = 0; c0 < 64; c0 += 4) {
        float4 xv[4];
#pragma unroll
        for (int u = 0; u < 4; ++u)
            xv[u] = *(const float4*)(xb + (size_t)(cbase + c0 + u) * NN + gn0);
#pragma unroll
        for (int u = 0; u < 4; ++u) {
            int c = cbase + c0 + u;
            float4 wa = *(const float4*)(wq_s + c * NH);
            float4 wb = *(const float4*)(wq_s + c * NH + 4);
            float xs[4] = {xv[u].x, xv[u].y, xv[u].z, xv[u].w};
            float ws[8] = {wa.x, wa.y, wa.z, wa.w, wb.x, wb.y, wb.z, wb.w};
#pragma unroll
            for (int i = 0; i < 4; ++i)
#pragma unroll
                for (int h = 0; h < NH; ++h) acc[i][h] += xs[i] * ws[h];
        }
    }

    // tree-reduce quarters: (1->0, 3->2), then (2->0). layout red4[buf*512 + k*64 + nt]
    if (q == 1 || q == 3) {
        int buf = (q == 1) ? 0 : 512;
#pragma unroll
        for (int i = 0; i < 4; ++i) {
            red4[buf + (i * 2 + 0) * 64 + nt] = make_float4(acc[i][0], acc[i][1], acc[i][2], acc[i][3]);
            red4[buf + (i * 2 + 1) * 64 + nt] = make_float4(acc[i][4], acc[i][5], acc[i][6], acc[i][7]);
        }
    }
    __syncthreads();
    if (q == 0 || q == 2) {
        int buf = (q == 0) ? 0 : 512;
#pragma unroll
        for (int i = 0; i < 4; ++i) {
            float4 r0 = red4[buf + (i * 2 + 0) * 64 + nt];
            float4 r1 = red4[buf + (i * 2 + 1) * 64 + nt];
            acc[i][0] += r0.x; acc[i][1] += r0.y; acc[i][2] += r0.z; acc[i][3] += r0.w;
            acc[i][4] += r1.x; acc[i][5] += r1.y; acc[i][6] += r1.z; acc[i][7] += r1.w;
        }
    }
    __syncthreads();
    if (q == 2) {
#pragma unroll
        for (int i = 0; i < 4; ++i) {
            red4[(i * 2 + 0) * 64 + nt] = make_float4(acc[i][0], acc[i][1], acc[i][2], acc[i][3]);
            red4[(i * 2 + 1) * 64 + nt] = make_float4(acc[i][4], acc[i][5], acc[i][6], acc[i][7]);
        }
    }
    __syncthreads();

    float v[4][NH];
    if (tid < 64) {
#pragma unroll
        for (int i = 0; i < 4; ++i) {
            float4 r0 = red4[(i * 2 + 0) * 64 + nt];
            float4 r1 = red4[(i * 2 + 1) * 64 + nt];
            v[i][0] = acc[i][0] + r0.x + cb_s[0]; v[i][1] = acc[i][1] + r0.y + cb_s[1];
            v[i][2] = acc[i][2] + r0.z + cb_s[2]; v[i][3] = acc[i][3] + r0.w + cb_s[3];
            v[i][4] = acc[i][4] + r1.x + cb_s[4]; v[i][5] = acc[i][5] + r1.y + cb_s[5];
            v[i][6] = acc[i][6] + r1.z + cb_s[6]; v[i][7] = acc[i][7] + r1.w + cb_s[7];
            float* dst = o_attn + ((size_t)b * NN + gn0 + i) * NH;
            *(float4*)dst = make_float4(v[i][0], v[i][1], v[i][2], v[i][3]);
            *(float4*)(dst + 4) = make_float4(v[i][4], v[i][5], v[i][6], v[i][7]);
        }
        float tm[NH];
#pragma unroll
        for (int h = 0; h < NH; ++h)
            tm[h] = fmaxf(fmaxf(v[0][h], v[1][h]), fmaxf(v[2][h], v[3][h]));
#pragma unroll
        for (int h = 0; h < NH; ++h)
#pragma unroll
            for (int m = 16; m; m >>= 1)
                tm[h] = fmaxf(tm[h], __shfl_xor_sync(0xffffffffu, tm[h], m));
        if ((nt & 31) == 0)
#pragma unroll
            for (int h = 0; h < NH; ++h) rs_max[nt >> 5][h] = tm[h];
    }
    __syncthreads();
    if (tid < NH) bmax[tid] = fmaxf(rs_max[0][tid], rs_max[1][tid]);
    __syncthreads();

    if (tid < 64) {
        float fx[4], fy[4];
#pragma unroll
        for (int i = 0; i < 4; ++i) {
            int n = gn0 + i;
            fx[i] = (float)(n >> 6); fy[i] = (float)(n & 63);
        }
        float r[24];
#pragma unroll
        for (int h = 0; h < NH; ++h) {
            float m = bmax[h];
            float e0 = __expf(v[0][h] - m), e1 = __expf(v[1][h] - m);
            float e2 = __expf(v[2][h] - m), e3 = __expf(v[3][h] - m);
            a_s4[h * 64 + nt] = make_float4(e0, e1, e2, e3);
            r[h]      = (e0 + e1) + (e2 + e3);
            r[8 + h]  = e0 * fx[0] + e1 * fx[1] + e2 * fx[2] + e3 * fx[3];
            r[16 + h] = e0 * fy[0] + e1 * fy[1] + e2 * fy[2] + e3 * fy[3];
        }
#pragma unroll
        for (int k = 0; k < 24; ++k)
#pragma unroll
            for (int m = 16; m; m >>= 1) r[k] += __shfl_xor_sync(0xffffffffu, r[k], m);
        if ((nt & 31) == 0)
#pragma unroll
            for (int k = 0; k < 24; ++k) rs_sum[nt >> 5][k] = r[k];
    }
    __syncthreads();
    if (tid < 24) {
        float* gp = g_part + ((size_t)b * NCH + ch) * 32;
        if (tid < 8) gp[tid] = bmax[tid];
        gp[8 + tid] = rs_sum[0][tid] + rs_sum[1][tid];
    }

    // ---- phase 2: partial xa (unnormalized, chunk-local max) — x tile is L2-hot
    int w = tid >> 5, l = tid & 31;
    const float* xb2 = xb + ch * CHN;
    float* xp = g_xap + ((size_t)b * NCH + ch) * CC * NH;
    const float* a_s = (const float*)a_s4;
#pragma unroll 1
    for (int it = 0; it < 8; ++it) {
        int c0 = it * 32 + w * 4;
        float pacc[NH][4];
#pragma unroll
        for (int h = 0; h < NH; ++h)
#pragma unroll
            for (int ci = 0; ci < 4; ++ci) pacc[h][ci] = 0.f;
#pragma unroll
        for (int j = 0; j < 2; ++j) {
            int nn = l * 4 + j * 128;
            float4 av[NH];
#pragma unroll
            for (int h = 0; h < NH; ++h) av[h] = *(const float4*)(a_s + h * CHN + nn);
#pragma unroll
            for (int ci = 0; ci < 4; ++ci) {
                float4 xv = *(const float4*)(xb2 + (size_t)(c0 + ci) * NN + nn);
#pragma unroll
                for (int h = 0; h < NH; ++h)
                    pacc[h][ci] += av[h].x * xv.x + av[h].y * xv.y +
                                   av[h].z * xv.z + av[h].w * xv.w;
            }
        }
#pragma unroll
        for (int h = 0; h < NH; ++h)
#pragma unroll
            for (int ci = 0; ci < 4; ++ci)
#pragma unroll
                for (int m = 16; m; m >>= 1)
                    pacc[h][ci] += __shfl_down_sync(0xffffffffu, pacc[h][ci], m);
        if (l == 0) {
#pragma unroll
            for (int ci = 0; ci < 4; ++ci)
#pragma unroll
                for (int h = 0; h < NH; ++h)
                    xp[(c0 + ci) * NH + h] = pacc[h][ci];
        }
    }
}

// ---------------- K4: logits -> attention (in place), global M/S inline --------
__global__ void k_attn(float* __restrict__ o_attn) {
    int b = blockIdx.y, seg = blockIdx.x;  // 8 segs x 512 n
    int tid = threadIdx.x;
    __shared__ float2 ms[NH];
    if (tid < NH) {
        const float* gp = g_part + (size_t)b * NCH * 32;
        float M = -3.4e38f;
#pragma unroll
        for (int c = 0; c < NCH; ++c) M = fmaxf(M, gp[c * 32 + tid]);
        float S = 0.f;
#pragma unroll
        for (int c = 0; c < NCH; ++c) S += gp[c * 32 + 8 + tid] * __expf(gp[c * 32 + tid] - M);
        ms[tid] = make_float2(M, 1.f / S);
    }
    __syncthreads();
    float* ab = o_attn + ((size_t)b * NN + seg * 512 + tid * 2) * NH;
    float4 p[4];
#pragma unroll
    for (int k = 0; k < 4; ++k) p[k] = *(const float4*)(ab + k * 4);
    float av[16] = {p[0].x,p[0].y,p[0].z,p[0].w, p[1].x,p[1].y,p[1].z,p[1].w,
                    p[2].x,p[2].y,p[2].z,p[2].w, p[3].x,p[3].y,p[3].z,p[3].w};
#pragma unroll
    for (int k = 0; k < 16; ++k) {
        int h = k & 7;
        av[k] = __expf(av[k] - ms[h].x) * ms[h].y;
    }
#pragma unroll
    for (int k = 0; k < 4; ++k)
        *(float4*)(ab + k * 4) = make_float4(av[k*4], av[k*4+1], av[k*4+2], av[k*4+3]);
}

// ---------------- K5: rescale-reduce xa, values GEMM, pos, batch, penalty ------
__global__ void k_values(const float* __restrict__ bv, float* __restrict__ o_values,
                         float* __restrict__ o_pos, float* __restrict__ o_batch,
                         float* __restrict__ o_pen) {
    int b = blockIdx.x;
    int tid = threadIdx.x;   // 256
    __shared__ float Mv[NH], iSv[NH];
    __shared__ float wch[NCH * NH];
    __shared__ float xa_s[CC * NH];   // [c][h]
    const float* gp = g_part + (size_t)b * NCH * 32;

    if (tid < NH) {
        float M = -3.4e38f;
#pragma unroll
        for (int c = 0; c < NCH; ++c) M = fmaxf(M, gp[c * 32 + tid]);
        float S = 0.f, PX = 0.f, PY = 0.f;
#pragma unroll
        for (int c = 0; c < NCH; ++c) {
            float e = __expf(gp[c * 32 + tid] - M);
            S  += gp[c * 32 + 8 + tid] * e;
            PX += gp[c * 32 + 16 + tid] * e;
            PY += gp[c * 32 + 24 + tid] * e;
        }
        float invS = 1.f / S;
        Mv[tid] = M; iSv[tid] = invS;
        o_pos[(b * NH + tid) * 2 + 0] = PX * invS;
        o_pos[(b * NH + tid) * 2 + 1] = PY * invS;
    }
    __syncthreads();
    if (tid < NCH * NH) {
        int c = tid >> 3, h = tid & 7;
        wch[tid] = __expf(gp[c * 32 + h] - Mv[h]) * iSv[h];
    }
    __syncthreads();
#pragma unroll
    for (int i = 0; i < 8; ++i) {
        int idx = i * 256 + tid;
        int h = idx & 7;
        float s = 0.f;
#pragma unroll
        for (int c = 0; c < NCH; ++c)
            s += g_xap[((size_t)b * NCH + c) * CC * NH + idx] * wch[c * NH + h];
        xa_s[idx] = s;
    }
    __syncthreads();
    float bve = bv[tid];
    float acc[NH];
#pragma unroll
    for (int h = 0; h < NH; ++h) acc[h] = bve;
#pragma unroll 4
    for (int c = 0; c < CC; ++c) {
        float wv = g_WvT[c * EE + tid];
#pragma unroll
        for (int h = 0; h < NH; ++h) acc[h] += xa_s[c * NH + h] * wv;
    }
#pragma unroll
    for (int h = 0; h < NH; ++h)
        o_values[((size_t)b * NH + h) * EE + tid] = acc[h];
    if (b == 0) {
        o_batch[tid] = (float)(tid >> 3);
        if (tid == 0) *o_pen = 0.f;
    }
}

// ---------------- launch ----------------
extern "C" void kernel_launch(void* const* d_in, const int* in_sizes, int n_in,
                              void* d_out, int out_size) {
    const float* x  = (const float*)d_in[0];
    const float* Wq = (const float*)d_in[1];
    const float* bq = (const float*)d_in[2];
    const float* Wk = (const float*)d_in[3];
    const float* bk = (const float*)d_in[4];
    const float* Wv = (const float*)d_in[5];
    const float* bv = (const float*)d_in[6];
    (void)in_sizes; (void)n_in; (void)out_size;

    float* out = (float*)d_out;
    float* o_values = out;                           // 65536
    float* o_pos    = o_values + BB * NH * EE;       // +512
    float* o_batch  = o_pos + BB * NH * 2;           // +256
    float* o_attn   = o_batch + BB * NH;             // +1048576
    float* o_pen    = o_attn + (size_t)BB * NN * NH; // +1

    k_mean_wvt<<<BB * CC + 256, 256>>>(x, Wv);
    k_qk      <<<BB, 256>>>(Wq, bq, Wk, bk);
    k_fused   <<<dim3(NCH, BB), 256>>>(x, o_attn);
    k_attn    <<<dim3(8, BB), 256>>>(o_attn);
    k_values  <<<BB, 256>>>(bv, o_values, o_pos, o_batch, o_pen);
}

// round 6
// speedup vs baseline: 1.0542x; 1.0542x over previous
#include <cuda_runtime.h>

#define BB 32
#define CC 256
#define NN 4096
#define EE 256
#define NH 8
#define HD 32
#define NCH 16     // n-chunks
#define CHN 256    // n per chunk

// ---------------- scratch ----------------
__device__ float g_mean[BB * CC];
__device__ float g_wq[BB * CC * NH];         // [b][c][h], pre-scaled by 1/sqrt(32)
__device__ float g_cbias[BB * NH];
__device__ float g_WvT[CC * EE];             // [c][e]
__device__ float g_part[BB * NCH * 32];      // per (b,ch): m[8], s[8], px[8], py[8]
__device__ float g_xap[BB * NCH * CC * NH];  // normalized partial xa: [c][h]

// ---------------- K1: spatial mean (+ Wv transpose in tail blocks) -------------
__global__ void k_mean_wvt(const float* __restrict__ x, const float* __restrict__ Wv) {
    if (blockIdx.x >= BB * CC) {
        int c = blockIdx.x - BB * CC;
        g_WvT[c * EE + threadIdx.x] = Wv[threadIdx.x * CC + c];
        return;
    }
    int row = blockIdx.x;
    const float4* xr = (const float4*)(x + (size_t)row * NN);
    float4 v0 = xr[threadIdx.x];
    float4 v1 = xr[threadIdx.x + 256];
    float4 v2 = xr[threadIdx.x + 512];
    float4 v3 = xr[threadIdx.x + 768];
    float s = ((v0.x + v0.y) + (v0.z + v0.w)) + ((v1.x + v1.y) + (v1.z + v1.w))
            + ((v2.x + v2.y) + (v2.z + v2.w)) + ((v3.x + v3.y) + (v3.z + v3.w));
#pragma unroll
    for (int m = 16; m; m >>= 1) s += __shfl_xor_sync(0xffffffffu, s, m);
    __shared__ float red[8];
    if ((threadIdx.x & 31) == 0) red[threadIdx.x >> 5] = s;
    __syncthreads();
    if (threadIdx.x == 0) {
        float t = red[0];
#pragma unroll
        for (int w = 1; w < 8; ++w) t += red[w];
        g_mean[row] = t * (1.f / NN);
    }
}

// ---------------- K2: q, wq_eff, cbias ----------------
__global__ void k_qk(const float* __restrict__ Wq, const float* __restrict__ bq,
                     const float* __restrict__ Wk, const float* __restrict__ bk) {
    int b = blockIdx.x;
    int tid = threadIdx.x;
    __shared__ float mean_s[CC];
    __shared__ float q_s[EE];
    mean_s[tid] = g_mean[b * CC + tid];
    __syncthreads();
    float acc = bq[tid];
    const float* wr = Wq + (size_t)tid * CC;
#pragma unroll 4
    for (int c = 0; c < CC; ++c) acc += mean_s[c] * wr[c];
    q_s[tid] = acc;
    __syncthreads();

    const float invs = 0.17677669529663689f; // 1/sqrt(32)
    int c = tid;
#pragma unroll
    for (int h = 0; h < NH; ++h) {
        float s = 0.f;
#pragma unroll 8
        for (int d = 0; d < HD; ++d)
            s += q_s[h * HD + d] * Wk[(size_t)(h * HD + d) * CC + c];
        g_wq[(b * CC + c) * NH + h] = s * invs;
    }
    if (tid < NH) {
        float s = 0.f;
        for (int d = 0; d < HD; ++d) s += q_s[tid * HD + d] * bk[tid * HD + d];
        g_cbias[b * NH + tid] = s * invs;
    }
}

// ---------------- K3: logits + per-chunk softmax stats + pos partials ----------
__global__ void __launch_bounds__(256) k_logits(const float* __restrict__ x,
                                                float* __restrict__ o_attn) {
    int b = blockIdx.y, ch = blockIdx.x;
    int tid = threadIdx.x;             // 256 threads
    int half = tid >> 7, nt = tid & 127;

    __shared__ float wq_s[CC * NH];    // 8 KB
    __shared__ float4 red4[4 * 128];   // 8 KB: cross-half partials
    __shared__ float cb_s[NH];
    __shared__ float rs[4 * 24];       // warp partials for s/px/py
    __shared__ float rs_max[4 * NH];
    __shared__ float bmax[NH];
    __shared__ float bsum[24];

#pragma unroll
    for (int i = 0; i < 8; ++i) wq_s[tid + i * 256] = g_wq[b * CC * NH + tid + i * 256];
    if (tid < NH) cb_s[tid] = g_cbias[b * NH + tid];
    __syncthreads();

    int n0 = ch * CHN + nt * 2;
    const float* xb = x + (size_t)b * CC * NN;
    float acc[2][NH];
#pragma unroll
    for (int i = 0; i < 2; ++i)
#pragma unroll
        for (int h = 0; h < NH; ++h) acc[i][h] = 0.f;

    int cbase = half * 128;
    for (int c0 = 0; c0 < 128; c0 += 4) {
        float2 xv[4];
#pragma unroll
        for (int u = 0; u < 4; ++u)
            xv[u] = *(const float2*)(xb + (size_t)(cbase + c0 + u) * NN + n0);
#pragma unroll
        for (int u = 0; u < 4; ++u) {
            int c = cbase + c0 + u;
            float4 wa = *(const float4*)(wq_s + c * NH);
            float4 wb = *(const float4*)(wq_s + c * NH + 4);
            float ws[8] = {wa.x, wa.y, wa.z, wa.w, wb.x, wb.y, wb.z, wb.w};
#pragma unroll
            for (int h = 0; h < NH; ++h) {
                acc[0][h] += xv[u].x * ws[h];
                acc[1][h] += xv[u].y * ws[h];
            }
        }
    }

    // cross-half reduce through smem (layout [k][nt], conflict-free)
    if (half == 1) {
#pragma unroll
        for (int i = 0; i < 2; ++i) {
            red4[(i * 2 + 0) * 128 + nt] = make_float4(acc[i][0], acc[i][1], acc[i][2], acc[i][3]);
            red4[(i * 2 + 1) * 128 + nt] = make_float4(acc[i][4], acc[i][5], acc[i][6], acc[i][7]);
        }
    }
    __syncthreads();

    float v[2][NH];
    if (half == 0) {
#pragma unroll
        for (int i = 0; i < 2; ++i) {
            float4 r0 = red4[(i * 2 + 0) * 128 + nt];
            float4 r1 = red4[(i * 2 + 1) * 128 + nt];
            v[i][0] = acc[i][0] + r0.x + cb_s[0]; v[i][1] = acc[i][1] + r0.y + cb_s[1];
            v[i][2] = acc[i][2] + r0.z + cb_s[2]; v[i][3] = acc[i][3] + r0.w + cb_s[3];
            v[i][4] = acc[i][4] + r1.x + cb_s[4]; v[i][5] = acc[i][5] + r1.y + cb_s[5];
            v[i][6] = acc[i][6] + r1.z + cb_s[6]; v[i][7] = acc[i][7] + r1.w + cb_s[7];
            float* dst = o_attn + ((size_t)b * NN + n0 + i) * NH;
            *(float4*)dst = make_float4(v[i][0], v[i][1], v[i][2], v[i][3]);
            *(float4*)(dst + 4) = make_float4(v[i][4], v[i][5], v[i][6], v[i][7]);
        }
        float tm[NH];
#pragma unroll
        for (int h = 0; h < NH; ++h) tm[h] = fmaxf(v[0][h], v[1][h]);
#pragma unroll
        for (int h = 0; h < NH; ++h)
#pragma unroll
            for (int m = 16; m; m >>= 1)
                tm[h] = fmaxf(tm[h], __shfl_xor_sync(0xffffffffu, tm[h], m));
        if ((nt & 31) == 0)
#pragma unroll
            for (int h = 0; h < NH; ++h) rs_max[(nt >> 5) * NH + h] = tm[h];
    }
    __syncthreads();
    if (tid < NH)
        bmax[tid] = fmaxf(fmaxf(rs_max[tid], rs_max[NH + tid]),
                          fmaxf(rs_max[2 * NH + tid], rs_max[3 * NH + tid]));
    __syncthreads();

    if (half == 0) {
        float fx0 = (float)(n0 >> 6), fy0 = (float)(n0 & 63);
        float fx1 = (float)((n0 + 1) >> 6), fy1 = (float)((n0 + 1) & 63);
        float r[24];
#pragma unroll
        for (int h = 0; h < NH; ++h) {
            float m = bmax[h];
            float e0 = __expf(v[0][h] - m), e1 = __expf(v[1][h] - m);
            r[h]      = e0 + e1;
            r[8 + h]  = e0 * fx0 + e1 * fx1;
            r[16 + h] = e0 * fy0 + e1 * fy1;
        }
#pragma unroll
        for (int k = 0; k < 24; ++k)
#pragma unroll
            for (int m = 16; m; m >>= 1) r[k] += __shfl_xor_sync(0xffffffffu, r[k], m);
        if ((nt & 31) == 0)
#pragma unroll
            for (int k = 0; k < 24; ++k) rs[(nt >> 5) * 24 + k] = r[k];
    }
    __syncthreads();
    if (tid < 24)
        bsum[tid] = rs[tid] + rs[24 + tid] + rs[48 + tid] + rs[72 + tid];
    __syncthreads();
    if (tid < NH) {
        float* gp = g_part + ((size_t)b * NCH + ch) * 32;
        gp[tid] = bmax[tid];
    }
    if (tid < 24) {
        float* gp = g_part + ((size_t)b * NCH + ch) * 32;
        gp[8 + tid] = bsum[tid];
    }
}

// ---------------- K4: apply softmax (write attention) + partial xa -------------
__global__ void __launch_bounds__(256) k_xa(const float* __restrict__ x,
                                            float* __restrict__ o_attn) {
    int b = blockIdx.y, ch = blockIdx.x;
    int tid = threadIdx.x;        // 256 = 8 warps
    int w = tid >> 5, l = tid & 31;
    __shared__ float a_s[NH * CHN];   // [h][n] 8 KB
    __shared__ float2 ms[NH];

    // inline global M, 1/S from chunk stats
    if (tid < NH) {
        const float* gp = g_part + (size_t)b * NCH * 32;
        float M = -3.4e38f;
#pragma unroll
        for (int c = 0; c < NCH; ++c) M = fmaxf(M, gp[c * 32 + tid]);
        float S = 0.f;
#pragma unroll
        for (int c = 0; c < NCH; ++c) S += gp[c * 32 + 8 + tid] * __expf(gp[c * 32 + tid] - M);
        ms[tid] = make_float2(M, 1.f / S);
    }
    __syncthreads();

    // stage 1: load logits (1 n per thread), softmax, write attention, stash smem
    float* ab = o_attn + ((size_t)b * NN + ch * CHN) * NH;
    {
        const float4* p = (const float4*)(ab + tid * NH);
        float4 p0 = p[0], p1 = p[1];
        float av[8] = {p0.x, p0.y, p0.z, p0.w, p1.x, p1.y, p1.z, p1.w};
#pragma unroll
        for (int h = 0; h < NH; ++h)
            av[h] = __expf(av[h] - ms[h].x) * ms[h].y;
        float4* q = (float4*)(ab + tid * NH);
        q[0] = make_float4(av[0], av[1], av[2], av[3]);
        q[1] = make_float4(av[4], av[5], av[6], av[7]);
#pragma unroll
        for (int h = 0; h < NH; ++h) a_s[h * CHN + tid] = av[h];
    }
    __syncthreads();

    // stage 2: partial xa over this n-chunk for all 256 channels (normalized)
    const float* xb = x + (size_t)b * CC * NN + ch * CHN;
    float* xp = g_xap + ((size_t)b * NCH + ch) * CC * NH;
#pragma unroll 1
    for (int it = 0; it < 8; ++it) {
        int c0 = it * 32 + w * 4;
        float acc[NH][4];
#pragma unroll
        for (int h = 0; h < NH; ++h)
#pragma unroll
            for (int ci = 0; ci < 4; ++ci) acc[h][ci] = 0.f;
#pragma unroll
        for (int j = 0; j < 2; ++j) {
            int nn = l * 4 + j * 128;
            float4 av[NH];
#pragma unroll
            for (int h = 0; h < NH; ++h) av[h] = *(const float4*)(a_s + h * CHN + nn);
#pragma unroll
            for (int ci = 0; ci < 4; ++ci) {
                float4 xv = *(const float4*)(xb + (size_t)(c0 + ci) * NN + nn);
#pragma unroll
                for (int h = 0; h < NH; ++h)
                    acc[h][ci] += av[h].x * xv.x + av[h].y * xv.y +
                                  av[h].z * xv.z + av[h].w * xv.w;
            }
        }
#pragma unroll
        for (int h = 0; h < NH; ++h)
#pragma unroll
            for (int ci = 0; ci < 4; ++ci)
#pragma unroll
                for (int m = 16; m; m >>= 1)
                    acc[h][ci] += __shfl_down_sync(0xffffffffu, acc[h][ci], m);
        if (l == 0) {
#pragma unroll
            for (int ci = 0; ci < 4; ++ci)
#pragma unroll
                for (int h = 0; h < NH; ++h)
                    xp[(c0 + ci) * NH + h] = acc[h][ci];
        }
    }
}

// ---------------- K5: reduce xa partials, values GEMM, pos, batch, penalty -----
__global__ void k_values(const float* __restrict__ bv, float* __restrict__ o_values,
                         float* __restrict__ o_pos, float* __restrict__ o_batch,
                         float* __restrict__ o_pen) {
    int b = blockIdx.x;
    int tid = threadIdx.x;   // 256
    __shared__ float xa_s[CC * NH];   // [c][h]
    const float* gp = g_part + (size_t)b * NCH * 32;

    if (tid < NH) {
        float M = -3.4e38f;
#pragma unroll
        for (int c = 0; c < NCH; ++c) M = fmaxf(M, gp[c * 32 + tid]);
        float S = 0.f, PX = 0.f, PY = 0.f;
#pragma unroll
        for (int c = 0; c < NCH; ++c) {
            float e = __expf(gp[c * 32 + tid] - M);
            S  += gp[c * 32 + 8 + tid] * e;
            PX += gp[c * 32 + 16 + tid] * e;
            PY += gp[c * 32 + 24 + tid] * e;
        }
        float invS = 1.f / S;
        o_pos[(b * NH + tid) * 2 + 0] = PX * invS;
        o_pos[(b * NH + tid) * 2 + 1] = PY * invS;
    }
    // partials are already normalized (k_xa used global M,S)
#pragma unroll
    for (int i = 0; i < 8; ++i) {
        int idx = i * 256 + tid;
        float s = 0.f;
#pragma unroll
        for (int c = 0; c < NCH; ++c)
            s += g_xap[((size_t)b * NCH + c) * CC * NH + idx];
        xa_s[idx] = s;
    }
    __syncthreads();
    float bve = bv[tid];
    float acc[NH];
#pragma unroll
    for (int h = 0; h < NH; ++h) acc[h] = bve;
#pragma unroll 4
    for (int c = 0; c < CC; ++c) {
        float wv = g_WvT[c * EE + tid];
#pragma unroll
        for (int h = 0; h < NH; ++h) acc[h] += xa_s[c * NH + h] * wv;
    }
#pragma unroll
    for (int h = 0; h < NH; ++h)
        o_values[((size_t)b * NH + h) * EE + tid] = acc[h];
    if (b == 0) {
        o_batch[tid] = (float)(tid >> 3);
        if (tid == 0) *o_pen = 0.f;
    }
}

// ---------------- launch ----------------
extern "C" void kernel_launch(void* const* d_in, const int* in_sizes, int n_in,
                              void* d_out, int out_size) {
    const float* x  = (const float*)d_in[0];
    const float* Wq = (const float*)d_in[1];
    const float* bq = (const float*)d_in[2];
    const float* Wk = (const float*)d_in[3];
    const float* bk = (const float*)d_in[4];
    const float* Wv = (const float*)d_in[5];
    const float* bv = (const float*)d_in[6];
    (void)in_sizes; (void)n_in; (void)out_size;

    float* out = (float*)d_out;
    float* o_values = out;                           // 65536
    float* o_pos    = o_values + BB * NH * EE;       // +512
    float* o_batch  = o_pos + BB * NH * 2;           // +256
    float* o_attn   = o_batch + BB * NH;             // +1048576
    float* o_pen    = o_attn + (size_t)BB * NN * NH; // +1

    k_mean_wvt<<<BB * CC + 256, 256>>>(x, Wv);
    k_qk      <<<BB, 256>>>(Wq, bq, Wk, bk);
    k_logits  <<<dim3(NCH, BB), 256>>>(x, o_attn);
    k_xa      <<<dim3(NCH, BB), 256>>>(x, o_attn);
    k_values  <<<BB, 256>>>(bv, o_values, o_pos, o_batch, o_pen);
}

// round 7
// speedup vs baseline: 1.0943x; 1.0380x over previous
#include <cuda_runtime.h>

#define BB 32
#define CC 256
#define NN 4096
#define EE 256
#define NH 8
#define HD 32
#define NCH 16     // n-chunks
#define CHN 256    // n per chunk

// ---------------- scratch ----------------
__device__ float g_mean[BB * CC];
__device__ float g_wq[BB * CC * NH];         // [b][c][h], pre-scaled by 1/sqrt(32)
__device__ float g_cbias[BB * NH];
__device__ float g_WvT[CC * EE];             // [c][e]
__device__ float g_part[BB * NCH * 32];      // per (b,ch): m[8], s[8], px[8], py[8]
__device__ float g_xap[BB * NCH * CC * NH];  // normalized partial xa: [c][h]

// ---------------- K1: spatial mean (+ Wv transpose in tail blocks) -------------
__global__ void k_mean_wvt(const float* __restrict__ x, const float* __restrict__ Wv) {
    if (blockIdx.x >= BB * CC) {
        int c = blockIdx.x - BB * CC;
        g_WvT[c * EE + threadIdx.x] = Wv[threadIdx.x * CC + c];
        return;
    }
    int row = blockIdx.x;
    const float4* xr = (const float4*)(x + (size_t)row * NN);
    float4 v0 = xr[threadIdx.x];
    float4 v1 = xr[threadIdx.x + 256];
    float4 v2 = xr[threadIdx.x + 512];
    float4 v3 = xr[threadIdx.x + 768];
    float s = ((v0.x + v0.y) + (v0.z + v0.w)) + ((v1.x + v1.y) + (v1.z + v1.w))
            + ((v2.x + v2.y) + (v2.z + v2.w)) + ((v3.x + v3.y) + (v3.z + v3.w));
#pragma unroll
    for (int m = 16; m; m >>= 1) s += __shfl_xor_sync(0xffffffffu, s, m);
    __shared__ float red[8];
    if ((threadIdx.x & 31) == 0) red[threadIdx.x >> 5] = s;
    __syncthreads();
    if (threadIdx.x == 0) {
        float t = red[0];
#pragma unroll
        for (int w = 1; w < 8; ++w) t += red[w];
        g_mean[row] = t * (1.f / NN);
    }
}

// ---------------- K2: q, wq_eff, cbias ----------------
__global__ void k_qk(const float* __restrict__ Wq, const float* __restrict__ bq,
                     const float* __restrict__ Wk, const float* __restrict__ bk) {
    int b = blockIdx.x;
    int tid = threadIdx.x;
    __shared__ float mean_s[CC];
    __shared__ float q_s[EE];
    mean_s[tid] = g_mean[b * CC + tid];
    __syncthreads();
    float acc = bq[tid];
    const float* wr = Wq + (size_t)tid * CC;
#pragma unroll 4
    for (int c = 0; c < CC; ++c) acc += mean_s[c] * wr[c];
    q_s[tid] = acc;
    __syncthreads();

    const float invs = 0.17677669529663689f; // 1/sqrt(32)
    int c = tid;
#pragma unroll
    for (int h = 0; h < NH; ++h) {
        float s = 0.f;
#pragma unroll 8
        for (int d = 0; d < HD; ++d)
            s += q_s[h * HD + d] * Wk[(size_t)(h * HD + d) * CC + c];
        g_wq[(b * CC + c) * NH + h] = s * invs;
    }
    if (tid < NH) {
        float s = 0.f;
        for (int d = 0; d < HD; ++d) s += q_s[tid * HD + d] * bk[tid * HD + d];
        g_cbias[b * NH + tid] = s * invs;
    }
}

// ---------------- K3: logits + per-chunk softmax stats + pos partials ----------
__global__ void __launch_bounds__(256) k_logits(const float* __restrict__ x,
                                                float* __restrict__ o_attn) {
    int b = blockIdx.y, ch = blockIdx.x;
    int tid = threadIdx.x;             // 256 threads
    int half = tid >> 7, nt = tid & 127;

    __shared__ float wq_s[CC * NH];    // 8 KB
    __shared__ float4 red4[4 * 128];   // 8 KB: cross-half partials
    __shared__ float cb_s[NH];
    __shared__ float rs[4 * 24];       // warp partials for s/px/py
    __shared__ float rs_max[4 * NH];
    __shared__ float bmax[NH];
    __shared__ float bsum[24];

#pragma unroll
    for (int i = 0; i < 8; ++i) wq_s[tid + i * 256] = g_wq[b * CC * NH + tid + i * 256];
    if (tid < NH) cb_s[tid] = g_cbias[b * NH + tid];
    __syncthreads();

    int n0 = ch * CHN + nt * 2;
    const float* xb = x + (size_t)b * CC * NN;
    float acc[2][NH];
#pragma unroll
    for (int i = 0; i < 2; ++i)
#pragma unroll
        for (int h = 0; h < NH; ++h) acc[i][h] = 0.f;

    int cbase = half * 128;
    for (int c0 = 0; c0 < 128; c0 += 4) {
        float2 xv[4];
#pragma unroll
        for (int u = 0; u < 4; ++u)
            xv[u] = *(const float2*)(xb + (size_t)(cbase + c0 + u) * NN + n0);
#pragma unroll
        for (int u = 0; u < 4; ++u) {
            int c = cbase + c0 + u;
            float4 wa = *(const float4*)(wq_s + c * NH);
            float4 wb = *(const float4*)(wq_s + c * NH + 4);
            float ws[8] = {wa.x, wa.y, wa.z, wa.w, wb.x, wb.y, wb.z, wb.w};
#pragma unroll
            for (int h = 0; h < NH; ++h) {
                acc[0][h] += xv[u].x * ws[h];
                acc[1][h] += xv[u].y * ws[h];
            }
        }
    }

    // cross-half reduce through smem (layout [k][nt], conflict-free)
    if (half == 1) {
#pragma unroll
        for (int i = 0; i < 2; ++i) {
            red4[(i * 2 + 0) * 128 + nt] = make_float4(acc[i][0], acc[i][1], acc[i][2], acc[i][3]);
            red4[(i * 2 + 1) * 128 + nt] = make_float4(acc[i][4], acc[i][5], acc[i][6], acc[i][7]);
        }
    }
    __syncthreads();

    float v[2][NH];
    if (half == 0) {
#pragma unroll
        for (int i = 0; i < 2; ++i) {
            float4 r0 = red4[(i * 2 + 0) * 128 + nt];
            float4 r1 = red4[(i * 2 + 1) * 128 + nt];
            v[i][0] = acc[i][0] + r0.x + cb_s[0]; v[i][1] = acc[i][1] + r0.y + cb_s[1];
            v[i][2] = acc[i][2] + r0.z + cb_s[2]; v[i][3] = acc[i][3] + r0.w + cb_s[3];
            v[i][4] = acc[i][4] + r1.x + cb_s[4]; v[i][5] = acc[i][5] + r1.y + cb_s[5];
            v[i][6] = acc[i][6] + r1.z + cb_s[6]; v[i][7] = acc[i][7] + r1.w + cb_s[7];
            float* dst = o_attn + ((size_t)b * NN + n0 + i) * NH;
            *(float4*)dst = make_float4(v[i][0], v[i][1], v[i][2], v[i][3]);
            *(float4*)(dst + 4) = make_float4(v[i][4], v[i][5], v[i][6], v[i][7]);
        }
        float tm[NH];
#pragma unroll
        for (int h = 0; h < NH; ++h) tm[h] = fmaxf(v[0][h], v[1][h]);
#pragma unroll
        for (int h = 0; h < NH; ++h)
#pragma unroll
            for (int m = 16; m; m >>= 1)
                tm[h] = fmaxf(tm[h], __shfl_xor_sync(0xffffffffu, tm[h], m));
        if ((nt & 31) == 0)
#pragma unroll
            for (int h = 0; h < NH; ++h) rs_max[(nt >> 5) * NH + h] = tm[h];
    }
    __syncthreads();
    if (tid < NH)
        bmax[tid] = fmaxf(fmaxf(rs_max[tid], rs_max[NH + tid]),
                          fmaxf(rs_max[2 * NH + tid], rs_max[3 * NH + tid]));
    __syncthreads();

    if (half == 0) {
        float fx0 = (float)(n0 >> 6), fy0 = (float)(n0 & 63);
        float fx1 = (float)((n0 + 1) >> 6), fy1 = (float)((n0 + 1) & 63);
        float r[24];
#pragma unroll
        for (int h = 0; h < NH; ++h) {
            float m = bmax[h];
            float e0 = __expf(v[0][h] - m), e1 = __expf(v[1][h] - m);
            r[h]      = e0 + e1;
            r[8 + h]  = e0 * fx0 + e1 * fx1;
            r[16 + h] = e0 * fy0 + e1 * fy1;
        }
#pragma unroll
        for (int k = 0; k < 24; ++k)
#pragma unroll
            for (int m = 16; m; m >>= 1) r[k] += __shfl_xor_sync(0xffffffffu, r[k], m);
        if ((nt & 31) == 0)
#pragma unroll
            for (int k = 0; k < 24; ++k) rs[(nt >> 5) * 24 + k] = r[k];
    }
    __syncthreads();
    if (tid < 24)
        bsum[tid] = rs[tid] + rs[24 + tid] + rs[48 + tid] + rs[72 + tid];
    __syncthreads();
    if (tid < NH) {
        float* gp = g_part + ((size_t)b * NCH + ch) * 32;
        gp[tid] = bmax[tid];
    }
    if (tid < 24) {
        float* gp = g_part + ((size_t)b * NCH + ch) * 32;
        gp[8 + tid] = bsum[tid];
    }
}

// ---------------- K4: apply softmax + partial xa (no shuffles) -----------------
// thread tid owns channel c=tid with acc[8] over heads; x staged in 32-n smem
// tiles (pitch 33 -> conflict-free scalar reads); attention staged [n][h].
__global__ void __launch_bounds__(256) k_xa(const float* __restrict__ x,
                                            float* __restrict__ o_attn) {
    int b = blockIdx.y, ch = blockIdx.x;
    int tid = threadIdx.x;        // 256
    __shared__ float a_t[CHN * 8];    // [n][h], pitch 8 : 8 KB
    __shared__ float xt[CC * 33];     // [c][32n + pad]  : 33 KB
    __shared__ float2 ms[NH];

    // global M, 1/S from chunk stats
    if (tid < NH) {
        const float* gp = g_part + (size_t)b * NCH * 32;
        float M = -3.4e38f;
#pragma unroll
        for (int c = 0; c < NCH; ++c) M = fmaxf(M, gp[c * 32 + tid]);
        float S = 0.f;
#pragma unroll
        for (int c = 0; c < NCH; ++c) S += gp[c * 32 + 8 + tid] * __expf(gp[c * 32 + tid] - M);
        ms[tid] = make_float2(M, 1.f / S);
    }
    __syncthreads();

    // stage 1: softmax-apply logits (1 n per thread), write attention, stash [n][h]
    float* ab = o_attn + ((size_t)b * NN + ch * CHN) * NH;
    {
        const float4* p = (const float4*)(ab + tid * NH);
        float4 p0 = p[0], p1 = p[1];
        float av[8] = {p0.x, p0.y, p0.z, p0.w, p1.x, p1.y, p1.z, p1.w};
#pragma unroll
        for (int h = 0; h < NH; ++h)
            av[h] = __expf(av[h] - ms[h].x) * ms[h].y;
        float4* q = (float4*)(ab + tid * NH);
        q[0] = make_float4(av[0], av[1], av[2], av[3]);
        q[1] = make_float4(av[4], av[5], av[6], av[7]);
        *(float4*)(a_t + tid * 8)     = make_float4(av[0], av[1], av[2], av[3]);
        *(float4*)(a_t + tid * 8 + 4) = make_float4(av[4], av[5], av[6], av[7]);
    }

    // stage 2: per-channel dot products, x staged in 8 sub-tiles of 32 n
    const float* xb = x + (size_t)b * CC * NN + ch * CHN;
    float acc[8];
#pragma unroll
    for (int h = 0; h < NH; ++h) acc[h] = 0.f;

#pragma unroll 1
    for (int ns = 0; ns < 8; ++ns) {
        __syncthreads();  // xt free (also orders a_t on first pass)
#pragma unroll
        for (int it = 0; it < 8; ++it) {
            int flat = it * 256 + tid;
            int c = flat >> 3, n4 = flat & 7;
            float4 v = *(const float4*)(xb + (size_t)c * NN + ns * 32 + n4 * 4);
            float* d = xt + c * 33 + n4 * 4;
            d[0] = v.x; d[1] = v.y; d[2] = v.z; d[3] = v.w;
        }
        __syncthreads();
        const float* arow = a_t + ns * 32 * 8;
        const float* xrow = xt + tid * 33;
#pragma unroll
        for (int n = 0; n < 32; ++n) {
            float4 a0 = *(const float4*)(arow + n * 8);
            float4 a1 = *(const float4*)(arow + n * 8 + 4);
            float xs = xrow[n];
            acc[0] += xs * a0.x; acc[1] += xs * a0.y;
            acc[2] += xs * a0.z; acc[3] += xs * a0.w;
            acc[4] += xs * a1.x; acc[5] += xs * a1.y;
            acc[6] += xs * a1.z; acc[7] += xs * a1.w;
        }
    }
    float* xp = g_xap + (((size_t)b * NCH + ch) * CC + tid) * NH;
    *(float4*)xp       = make_float4(acc[0], acc[1], acc[2], acc[3]);
    *(float4*)(xp + 4) = make_float4(acc[4], acc[5], acc[6], acc[7]);
}

// ---------------- K5: reduce xa partials, values GEMM, pos, batch, penalty -----
// grid (BB, 2): blockIdx.y selects h-half [hh*4, hh*4+4)
__global__ void k_values(const float* __restrict__ bv, float* __restrict__ o_values,
                         float* __restrict__ o_pos, float* __restrict__ o_batch,
                         float* __restrict__ o_pen) {
    int b = blockIdx.x, hh = blockIdx.y;
    int tid = threadIdx.x;   // 256
    __shared__ float xa_s[CC * 4];   // [c][4h of this half]
    const float* gp = g_part + (size_t)b * NCH * 32;

    if (hh == 0 && tid < NH) {
        float M = -3.4e38f;
#pragma unroll
        for (int c = 0; c < NCH; ++c) M = fmaxf(M, gp[c * 32 + tid]);
        float S = 0.f, PX = 0.f, PY = 0.f;
#pragma unroll
        for (int c = 0; c < NCH; ++c) {
            float e = __expf(gp[c * 32 + tid] - M);
            S  += gp[c * 32 + 8 + tid] * e;
            PX += gp[c * 32 + 16 + tid] * e;
            PY += gp[c * 32 + 24 + tid] * e;
        }
        float invS = 1.f / S;
        o_pos[(b * NH + tid) * 2 + 0] = PX * invS;
        o_pos[(b * NH + tid) * 2 + 1] = PY * invS;
    }
    // reduce normalized partials for this h-half
#pragma unroll
    for (int i = 0; i < 4; ++i) {
        int idx = i * 256 + tid;          // c*4 + h4
        int c = idx >> 2, h4 = idx & 3;
        float s = 0.f;
#pragma unroll
        for (int cch = 0; cch < NCH; ++cch)
            s += g_xap[((size_t)b * NCH + cch) * CC * NH + c * NH + hh * 4 + h4];
        xa_s[idx] = s;
    }
    __syncthreads();
    float bve = bv[tid];
    float acc[4];
#pragma unroll
    for (int j = 0; j < 4; ++j) acc[j] = bve;
#pragma unroll 4
    for (int c = 0; c < CC; ++c) {
        float wv = g_WvT[c * EE + tid];
#pragma unroll
        for (int j = 0; j < 4; ++j) acc[j] += xa_s[c * 4 + j] * wv;
    }
#pragma unroll
    for (int j = 0; j < 4; ++j)
        o_values[((size_t)b * NH + hh * 4 + j) * EE + tid] = acc[j];
    if (b == 0 && hh == 0) {
        o_batch[tid] = (float)(tid >> 3);
        if (tid == 0) *o_pen = 0.f;
    }
}

// ---------------- launch ----------------
extern "C" void kernel_launch(void* const* d_in, const int* in_sizes, int n_in,
                              void* d_out, int out_size) {
    const float* x  = (const float*)d_in[0];
    const float* Wq = (const float*)d_in[1];
    const float* bq = (const float*)d_in[2];
    const float* Wk = (const float*)d_in[3];
    const float* bk = (const float*)d_in[4];
    const float* Wv = (const float*)d_in[5];
    const float* bv = (const float*)d_in[6];
    (void)in_sizes; (void)n_in; (void)out_size;

    float* out = (float*)d_out;
    float* o_values = out;                           // 65536
    float* o_pos    = o_values + BB * NH * EE;       // +512
    float* o_batch  = o_pos + BB * NH * 2;           // +256
    float* o_attn   = o_batch + BB * NH;             // +1048576
    float* o_pen    = o_attn + (size_t)BB * NN * NH; // +1

    k_mean_wvt<<<BB * CC + 256, 256>>>(x, Wv);
    k_qk      <<<BB, 256>>>(Wq, bq, Wk, bk);
    k_logits  <<<dim3(NCH, BB), 256>>>(x, o_attn);
    k_xa      <<<dim3(NCH, BB), 256>>>(x, o_attn);
    k_values  <<<dim3(BB, 2), 256>>>(bv, o_values, o_pos, o_batch, o_pen);
}